// round 9
// baseline (speedup 1.0000x reference)
#include <cuda_runtime.h>
#include <cuda_fp16.h>
#include <cuda_fp8.h>

#define NN 8192
#define EPSI 0.1f
#define NITERS 50
#define NBLK 148            // one block per SM — all co-resident (required for grid barrier)
#define THREADS 512
#define BATCH 8             // rows per stage
#define NBATCH 7            // 56 rows per block
#define STAGE_BYTES (BATCH * NN)                    // 65536
#define SMEMSZ (2 * STAGE_BYTES + 16 + (64 + 256) * 4)

// K = exp(M/eps) as e5m2 fp8 (range [1, 22026.5] fits; decode = byte<<8 == fp16). 64MB.
__device__ __align__(16) unsigned char dK8[(size_t)NN * NN];
__device__ float dU[NN];                       // true u of final iteration (for loss)
__device__ __align__(16) float dVglob[NN];     // v (unscaled fp32), rewritten per iteration
__device__ __align__(16) float dScr[NBLK][NN]; // per-block colAcc partials (x 2^31)
__device__ float dColAccLast[NN];
__device__ float dR[NN];                       // row sums of target
__device__ float dCs[NN];                      // col sums of target
__device__ float dDot;                         // sum(target * M)
__device__ unsigned int gCount;                // grid barrier state (reset by init_kernel)
__device__ unsigned int gEpoch;

__device__ __forceinline__ __half2 e5lo(unsigned int x) {
    unsigned int r = __byte_perm(x, 0u, 0x1404);
    return *reinterpret_cast<__half2*>(&r);
}
__device__ __forceinline__ __half2 e5hi(unsigned int x) {
    unsigned int r = __byte_perm(x, 0u, 0x3424);
    return *reinterpret_cast<__half2*>(&r);
}
__device__ __forceinline__ unsigned long long pol_last() {
    unsigned long long p;
    asm("createpolicy.fractional.L2::evict_last.b64 %0, 1.0;" : "=l"(p));
    return p;
}
__device__ __forceinline__ unsigned long long pol_first() {
    unsigned long long p;
    asm("createpolicy.fractional.L2::evict_first.b64 %0, 1.0;" : "=l"(p));
    return p;
}
__device__ __forceinline__ void stK(unsigned char* p, uint2 v, unsigned long long pol) {
    asm volatile("st.global.L2::cache_hint.v2.u32 [%0], {%1,%2}, %3;"
                 :: "l"(p), "r"(v.x), "r"(v.y), "l"(pol) : "memory");
}
__device__ __forceinline__ float4 ldS(const float* p, unsigned long long pol) {
    float4 v;
    asm volatile("ld.global.nc.L2::cache_hint.v4.f32 {%0,%1,%2,%3}, [%4], %5;"
                 : "=f"(v.x), "=f"(v.y), "=f"(v.z), "=f"(v.w) : "l"(p), "l"(pol));
    return v;
}

// ---- mbarrier / TMA bulk helpers ----
__device__ __forceinline__ void mbar_init(unsigned int m, unsigned int cnt) {
    asm volatile("mbarrier.init.shared.b64 [%0], %1;" :: "r"(m), "r"(cnt) : "memory");
}
__device__ __forceinline__ void mbar_expect_tx(unsigned int m, unsigned int tx) {
    asm volatile("mbarrier.arrive.expect_tx.shared.b64 _, [%0], %1;"
                 :: "r"(m), "r"(tx) : "memory");
}
__device__ __forceinline__ void mbar_wait(unsigned int m, unsigned int parity) {
    asm volatile(
        "{\n\t.reg .pred P;\n\t"
        "WL_%=:\n\t"
        "mbarrier.try_wait.parity.acquire.cta.shared::cta.b64 P, [%0], %1, 0x989680;\n\t"
        "@P bra.uni WD_%=;\n\t"
        "bra.uni WL_%=;\n\t"
        "WD_%=:\n\t}"
        :: "r"(m), "r"(parity) : "memory");
}
__device__ __forceinline__ void tma_bulk(unsigned int dst, const void* src,
                                         unsigned int bytes, unsigned int mbar) {
    asm volatile(
        "cp.async.bulk.shared::cluster.global.mbarrier::complete_tx::bytes [%0], [%1], %2, [%3];"
        :: "r"(dst), "l"(src), "r"(bytes), "r"(mbar) : "memory");
}

// epoch grid barrier: all NBLK blocks co-resident; target = 1-indexed barrier number.
__device__ __forceinline__ void gridbar(int t, unsigned int target) {
    __syncthreads();
    if (t == 0) {
        __threadfence();
        if (atomicAdd(&gCount, 1u) == NBLK - 1) {
            atomicExch(&gCount, 0u);
            __threadfence();
            atomicAdd(&gEpoch, 1u);
        } else {
            while (atomicAdd(&gEpoch, 0u) < target) {}
        }
        __threadfence();
    }
    __syncthreads();
}

__global__ void init_kernel() {
    int j = blockIdx.x * blockDim.x + threadIdx.x;
    if (j < NN) {
        dR[j] = 0.f;
        dCs[j] = 0.f;
        dVglob[j] = 1.0f;                  // v_0 = 1
    }
    if (j == 0) { dDot = 0.f; gCount = 0u; gEpoch = 0u; }
}

// One pass over M and target: build K (e5m2), row/col sums of target, dot(target, M).
__global__ void __launch_bounds__(256) prep_kernel(const float* __restrict__ M,
                                                   const float* __restrict__ T) {
    __shared__ float sred[8 * 256];
    __shared__ float sdot_s[256];
    const unsigned long long pF = pol_first();
    const unsigned long long pL = pol_last();
    const int w = threadIdx.x >> 5, l = threadIdx.x & 31;
    const int col0 = blockIdx.x * 256 + l * 8;
    const int r0 = blockIdx.y * 256;
    const float SC = 10.0f * 1.4426950408889634f;

    float cs[8];
#pragma unroll
    for (int k = 0; k < 8; k++) cs[k] = 0.f;
    float dot = 0.f;

    for (int r = r0 + w; r < r0 + 256; r += 8) {
        size_t base = (size_t)r * NN + col0;
        float4 m0 = ldS(M + base, pF);
        float4 m1 = ldS(M + base + 4, pF);
        float4 t0 = ldS(T + base, pF);
        float4 t1 = ldS(T + base + 4, pF);

        union { uint2 u; __nv_fp8x2_storage_t s[4]; } P;
        P.s[0] = __nv_cvt_float2_to_fp8x2(make_float2(exp2f(m0.x * SC), exp2f(m0.y * SC)),
                                          __NV_SATFINITE, __NV_E5M2);
        P.s[1] = __nv_cvt_float2_to_fp8x2(make_float2(exp2f(m0.z * SC), exp2f(m0.w * SC)),
                                          __NV_SATFINITE, __NV_E5M2);
        P.s[2] = __nv_cvt_float2_to_fp8x2(make_float2(exp2f(m1.x * SC), exp2f(m1.y * SC)),
                                          __NV_SATFINITE, __NV_E5M2);
        P.s[3] = __nv_cvt_float2_to_fp8x2(make_float2(exp2f(m1.z * SC), exp2f(m1.w * SC)),
                                          __NV_SATFINITE, __NV_E5M2);
        stK(dK8 + base, P.u, pL);

        cs[0] += t0.x; cs[1] += t0.y; cs[2] += t0.z; cs[3] += t0.w;
        cs[4] += t1.x; cs[5] += t1.y; cs[6] += t1.z; cs[7] += t1.w;

        dot += m0.x * t0.x + m0.y * t0.y + m0.z * t0.z + m0.w * t0.w
             + m1.x * t1.x + m1.y * t1.y + m1.z * t1.z + m1.w * t1.w;

        float rs = t0.x + t0.y + t0.z + t0.w + t1.x + t1.y + t1.z + t1.w;
#pragma unroll
        for (int o = 16; o > 0; o >>= 1) rs += __shfl_xor_sync(0xffffffffu, rs, o);
        if (l == 0) atomicAdd(&dR[r], rs);
    }

#pragma unroll
    for (int k = 0; k < 8; k++) sred[w * 256 + l * 8 + k] = cs[k];
    sdot_s[threadIdx.x] = dot;
    __syncthreads();

    float s = 0.f;
#pragma unroll
    for (int w2 = 0; w2 < 8; w2++) s += sred[w2 * 256 + threadIdx.x];
    atomicAdd(&dCs[blockIdx.x * 256 + threadIdx.x], s);

    for (int off = 128; off > 0; off >>= 1) {
        if (threadIdx.x < off) sdot_s[threadIdx.x] += sdot_s[threadIdx.x + off];
        __syncthreads();
    }
    if (threadIdx.x == 0) atomicAdd(&dDot, sdot_s[0]);
}

// Persistent fused Sinkhorn: all 50 iterations in one kernel. Per iteration,
// one sweep over this block's 56 rows of K (TMA-bulk double-buffered through
// smem) computes u_i = a_i/(K_i.v) and colAcc partials; a device grid barrier
// then lets each block reduce its column slice to produce the next v.
__global__ void __launch_bounds__(THREADS, 1)
sinkhorn_persist(const float* __restrict__ a, const float* __restrict__ b) {
    extern __shared__ char smem[];
    unsigned int sbase;
    asm("{ .reg .u64 tmp; cvta.to.shared.u64 tmp, %1; cvt.u32.u64 %0, tmp; }"
        : "=r"(sbase) : "l"(smem));
    const unsigned int mbar0 = sbase + 2 * STAGE_BYTES;          // two u64 mbarriers
    float* sa   = reinterpret_cast<float*>(smem + 2 * STAGE_BYTES + 16);   // [64]
    float* sdot = sa + 64;                                                 // [2][128]

    const int t = threadIdx.x;
    const int l = t & 31;
    const int w = t >> 5;
    const int c0 = t * 16;
    const int bid = blockIdx.x;
    const int r0 = (bid * NN) / NBLK;
    const int r1 = ((bid + 1) * NN) / NBLK;   // 55 or 56 rows
    const int cs = r0, ce = r1;               // column slice for reduce = same split

    if (t == 0) {
        mbar_init(mbar0, 1);
        mbar_init(mbar0 + 8, 1);
        asm volatile("fence.proxy.async.shared::cta;" ::: "memory");
    }
    if (t < 64) {
        int rr = r0 + t;
        sa[t] = (rr < r1) ? a[rr] * 0.00390625f : 0.f;   // a * 2^-8
    }
    __syncthreads();

    // prologue: fill both stages (batches 0 and 1)
    if (t == 0) {
#pragma unroll
        for (int s = 0; s < 2; s++) {
            mbar_expect_tx(mbar0 + 8 * s, STAGE_BYTES);
            const unsigned char* src = dK8 + (size_t)(r0 + s * BATCH) * NN;
#pragma unroll
            for (int q = 0; q < 4; q++)
                tma_bulk(sbase + s * STAGE_BYTES + q * 16384, src + q * 16384,
                         16384, mbar0 + 8 * s);
        }
    }

    // v (scaled 2^-8) for my 16 columns -> 8 half2 regs
    __half2 V[8];
    {
        float4 v0 = __ldcg(reinterpret_cast<const float4*>(dVglob + c0));
        float4 v1 = __ldcg(reinterpret_cast<const float4*>(dVglob + c0 + 4));
        float4 v2 = __ldcg(reinterpret_cast<const float4*>(dVglob + c0 + 8));
        float4 v3 = __ldcg(reinterpret_cast<const float4*>(dVglob + c0 + 12));
        const float S8 = 0.00390625f;
        V[0] = __floats2half2_rn(v0.x * S8, v0.y * S8);
        V[1] = __floats2half2_rn(v0.z * S8, v0.w * S8);
        V[2] = __floats2half2_rn(v1.x * S8, v1.y * S8);
        V[3] = __floats2half2_rn(v1.z * S8, v1.w * S8);
        V[4] = __floats2half2_rn(v2.x * S8, v2.y * S8);
        V[5] = __floats2half2_rn(v2.z * S8, v2.w * S8);
        V[6] = __floats2half2_rn(v3.x * S8, v3.y * S8);
        V[7] = __floats2half2_rn(v3.z * S8, v3.w * S8);
    }

    int cnt = 0;                                 // global batch counter (350 total)
    for (int it = 0; it < NITERS; it++) {
        float facc[16];
#pragma unroll
        for (int i = 0; i < 16; i++) facc[i] = 0.f;

#pragma unroll 1
        for (int bt = 0; bt < NBATCH; bt++, cnt++) {
            const int s = cnt & 1;
            mbar_wait(mbar0 + 8 * s, (cnt >> 1) & 1);

            const uint4* sp = reinterpret_cast<const uint4*>(smem + s * STAGE_BYTES) + t;
            uint4 kq[BATCH];
#pragma unroll
            for (int r = 0; r < BATCH; r++) kq[r] = sp[r * 512];

            // Phase A: per-row partial dots with v
            float dotp[BATCH];
#pragma unroll
            for (int r = 0; r < BATCH; r++) {
                __half2 hs = __hmul2(e5lo(kq[r].x), V[0]);
                hs = __hfma2(e5hi(kq[r].x), V[1], hs);
                hs = __hfma2(e5lo(kq[r].y), V[2], hs);
                hs = __hfma2(e5hi(kq[r].y), V[3], hs);
                hs = __hfma2(e5lo(kq[r].z), V[4], hs);
                hs = __hfma2(e5hi(kq[r].z), V[5], hs);
                hs = __hfma2(e5lo(kq[r].w), V[6], hs);
                hs = __hfma2(e5hi(kq[r].w), V[7], hs);
                float2 f = __half22float2(hs);
                dotp[r] = f.x + f.y;
            }
#pragma unroll
            for (int r = 0; r < BATCH; r++) {
#pragma unroll
                for (int o = 16; o > 0; o >>= 1)
                    dotp[r] += __shfl_xor_sync(0xffffffffu, dotp[r], o);
            }
            const int par = cnt & 1;
            if (l == 0) {
#pragma unroll
                for (int r = 0; r < BATCH; r++) sdot[par * 128 + r * 16 + w] = dotp[r];
            }
            __syncthreads();      // everyone consumed stage s regs AND sdot visible

            // refill stage s for batch cnt+2 (same stage parity)
            if (t == 0 && cnt + 2 < NITERS * NBATCH) {
                const int bt2 = (cnt + 2) % NBATCH;
                mbar_expect_tx(mbar0 + 8 * s, STAGE_BYTES);
                const unsigned char* src = dK8 + (size_t)(r0 + bt2 * BATCH) * NN;
#pragma unroll
                for (int q = 0; q < 4; q++)
                    tma_bulk(sbase + s * STAGE_BYTES + q * 16384, src + q * 16384,
                             16384, mbar0 + 8 * s);
            }

            // every warp redundantly reduces the 8x16 partials
            float x0 = sdot[par * 128 + l];
            float x1 = sdot[par * 128 + 32 + l];
            float x2 = sdot[par * 128 + 64 + l];
            float x3 = sdot[par * 128 + 96 + l];
#pragma unroll
            for (int o = 8; o > 0; o >>= 1) {
                x0 += __shfl_xor_sync(0xffffffffu, x0, o);
                x1 += __shfl_xor_sync(0xffffffffu, x1, o);
                x2 += __shfl_xor_sync(0xffffffffu, x2, o);
                x3 += __shfl_xor_sync(0xffffffffu, x3, o);
            }
            const int rb = r0 + bt * BATCH;
            const int half16 = l >> 4;
            const int my0 = rb + 0 + half16;
            const int my1 = rb + 2 + half16;
            const int my2 = rb + 4 + half16;
            const int my3 = rb + 6 + half16;
            float u0 = (my0 < r1) ? __fdividef(sa[my0 - r0], x0) : 0.f;
            float u1 = (my1 < r1) ? __fdividef(sa[my1 - r0], x1) : 0.f;
            float u2 = (my2 < r1) ? __fdividef(sa[my2 - r0], x2) : 0.f;
            float u3 = (my3 < r1) ? __fdividef(sa[my3 - r0], x3) : 0.f;
            if (it == NITERS - 1 && (t == 0 || t == 16)) {
                if (my0 < r1) dU[my0] = u0;
                if (my1 < r1) dU[my1] = u1;
                if (my2 < r1) dU[my2] = u2;
                if (my3 < r1) dU[my3] = u3;
            }
            const float S31 = 2147483648.0f;
            __half2 uh[BATCH];
            uh[0] = __float2half2_rn(__shfl_sync(0xffffffffu, u0, 0) * S31);
            uh[1] = __float2half2_rn(__shfl_sync(0xffffffffu, u0, 16) * S31);
            uh[2] = __float2half2_rn(__shfl_sync(0xffffffffu, u1, 0) * S31);
            uh[3] = __float2half2_rn(__shfl_sync(0xffffffffu, u1, 16) * S31);
            uh[4] = __float2half2_rn(__shfl_sync(0xffffffffu, u2, 0) * S31);
            uh[5] = __float2half2_rn(__shfl_sync(0xffffffffu, u2, 16) * S31);
            uh[6] = __float2half2_rn(__shfl_sync(0xffffffffu, u3, 0) * S31);
            uh[7] = __float2half2_rn(__shfl_sync(0xffffffffu, u3, 16) * S31);

            // Phase B: colAcc partials += K^T u
            __half2 bacc[8];
#pragma unroll
            for (int i = 0; i < 8; i++) bacc[i] = __float2half2_rn(0.f);
#pragma unroll
            for (int r = 0; r < BATCH; r++) {
                bacc[0] = __hfma2(e5lo(kq[r].x), uh[r], bacc[0]);
                bacc[1] = __hfma2(e5hi(kq[r].x), uh[r], bacc[1]);
                bacc[2] = __hfma2(e5lo(kq[r].y), uh[r], bacc[2]);
                bacc[3] = __hfma2(e5hi(kq[r].y), uh[r], bacc[3]);
                bacc[4] = __hfma2(e5lo(kq[r].z), uh[r], bacc[4]);
                bacc[5] = __hfma2(e5hi(kq[r].z), uh[r], bacc[5]);
                bacc[6] = __hfma2(e5lo(kq[r].w), uh[r], bacc[6]);
                bacc[7] = __hfma2(e5hi(kq[r].w), uh[r], bacc[7]);
            }
#pragma unroll
            for (int i = 0; i < 8; i++) {
                float2 f = __half22float2(bacc[i]);
                facc[2 * i]     += f.x;
                facc[2 * i + 1] += f.y;
            }
        }

        // publish partials (x 2^31)
        float4* outp = reinterpret_cast<float4*>(&dScr[bid][c0]);
#pragma unroll
        for (int i = 0; i < 4; i++)
            outp[i] = make_float4(facc[4 * i], facc[4 * i + 1],
                                  facc[4 * i + 2], facc[4 * i + 3]);
        __threadfence();
        gridbar(t, 2 * it + 1);

        // reduce my column slice: 8 threads per column, 19 partials each
        if (t < 448) {
            const int col = cs + min(t >> 3, ce - cs - 1);
            const int sub = t & 7;
            const int p1 = min(sub * 19 + 19, NBLK);
            float s = 0.f;
            for (int p = sub * 19; p < p1; p++) s += __ldcg(&dScr[p][col]);
            s += __shfl_xor_sync(0xffffffffu, s, 4);
            s += __shfl_xor_sync(0xffffffffu, s, 2);
            s += __shfl_xor_sync(0xffffffffu, s, 1);
            if (sub == 0) {
                float tot = s * (1.0f / 2147483648.0f);
                dColAccLast[col] = tot;
                dVglob[col] = __fdividef(b[col], tot);
            }
        }
        __threadfence();
        gridbar(t, 2 * it + 2);

        // reload v for next iteration
        if (it < NITERS - 1) {
            float4 v0 = __ldcg(reinterpret_cast<const float4*>(dVglob + c0));
            float4 v1 = __ldcg(reinterpret_cast<const float4*>(dVglob + c0 + 4));
            float4 v2 = __ldcg(reinterpret_cast<const float4*>(dVglob + c0 + 8));
            float4 v3 = __ldcg(reinterpret_cast<const float4*>(dVglob + c0 + 12));
            const float S8 = 0.00390625f;
            V[0] = __floats2half2_rn(v0.x * S8, v0.y * S8);
            V[1] = __floats2half2_rn(v0.z * S8, v0.w * S8);
            V[2] = __floats2half2_rn(v1.x * S8, v1.y * S8);
            V[3] = __floats2half2_rn(v1.z * S8, v1.w * S8);
            V[4] = __floats2half2_rn(v2.x * S8, v2.y * S8);
            V[5] = __floats2half2_rn(v2.z * S8, v2.w * S8);
            V[6] = __floats2half2_rn(v3.x * S8, v3.y * S8);
            V[7] = __floats2half2_rn(v3.z * S8, v3.w * S8);
        }
    }
}

// loss = -( dot(target,M)/eps + sum_i R_i ln u_i + sum_j C_j ln v_j )
__global__ void loss_kernel(const float* __restrict__ b, float* __restrict__ out) {
    __shared__ float sred[1024];
    float p = 0.f;
    for (int i = threadIdx.x; i < NN; i += 1024) {
        p += dR[i] * logf(dU[i]);
        p += dCs[i] * (logf(b[i]) - logf(dColAccLast[i]));
    }
    sred[threadIdx.x] = p;
    __syncthreads();
    for (int off = 512; off > 0; off >>= 1) {
        if (threadIdx.x < off) sred[threadIdx.x] += sred[threadIdx.x + off];
        __syncthreads();
    }
    if (threadIdx.x == 0) out[0] = -(sred[0] + dDot * (1.0f / EPSI));
}

extern "C" void kernel_launch(void* const* d_in, const int* in_sizes, int n_in,
                              void* d_out, int out_size) {
    const float* M = (const float*)d_in[0];
    const float* T = (const float*)d_in[1];
    const float* a = (const float*)d_in[2];
    const float* b = (const float*)d_in[3];
    float* out = (float*)d_out;

    static int smem_set = 0;
    if (!smem_set) {
        cudaFuncSetAttribute(sinkhorn_persist,
                             cudaFuncAttributeMaxDynamicSharedMemorySize, SMEMSZ);
        smem_set = 1;
    }

    init_kernel<<<(NN + 255) / 256, 256>>>();
    prep_kernel<<<dim3(32, 32), 256>>>(M, T);
    sinkhorn_persist<<<NBLK, THREADS, SMEMSZ>>>(a, b);
    loss_kernel<<<1, 1024>>>(b, out);
}

// round 10
// speedup vs baseline: 1.1863x; 1.1863x over previous
#include <cuda_runtime.h>
#include <cuda_fp16.h>
#include <cuda_fp8.h>

#define NN 8192
#define EPSI 0.1f
#define NITERS 50
#define NBLK 148            // one block per SM
#define THREADS 512
#define BATCH 8             // rows per pipeline stage
#define NBATCH 7            // 56 rows per block max (pad with duplicate row, u=0)
#define STAGE_BYTES (BATCH * NN)   // 65536
#define SMEMSZ (2 * STAGE_BYTES + 16 + (64 + 256) * 4)

// K = exp(M/eps) as e5m2 fp8 (range [1, 22026.5] fits; decode = byte<<8 == fp16). 64MB.
__device__ __align__(16) unsigned char dK8[(size_t)NN * NN];
__device__ float dU[NN];                                 // true u of current iteration
__device__ __align__(16) __half dVh[(NITERS + 1) * NN];  // v * 2^-8 per iteration
__device__ __align__(16) float dScr[NBLK][NN];           // per-block colAcc partials (x 2^31)
__device__ float dColAccLast[NN];
__device__ float dR[NN];                                 // row sums of target
__device__ float dCs[NN];                                // col sums of target
__device__ float dDot;                                   // sum(target * M)

__device__ __forceinline__ __half2 e5lo(unsigned int x) {
    unsigned int r = __byte_perm(x, 0u, 0x1404);
    return *reinterpret_cast<__half2*>(&r);
}
__device__ __forceinline__ __half2 e5hi(unsigned int x) {
    unsigned int r = __byte_perm(x, 0u, 0x3424);
    return *reinterpret_cast<__half2*>(&r);
}
__device__ __forceinline__ unsigned long long pol_last() {
    unsigned long long p;
    asm("createpolicy.fractional.L2::evict_last.b64 %0, 1.0;" : "=l"(p));
    return p;
}
__device__ __forceinline__ unsigned long long pol_first() {
    unsigned long long p;
    asm("createpolicy.fractional.L2::evict_first.b64 %0, 1.0;" : "=l"(p));
    return p;
}
__device__ __forceinline__ void stK(unsigned char* p, uint2 v, unsigned long long pol) {
    asm volatile("st.global.L2::cache_hint.v2.u32 [%0], {%1,%2}, %3;"
                 :: "l"(p), "r"(v.x), "r"(v.y), "l"(pol) : "memory");
}
__device__ __forceinline__ float4 ldS(const float* p, unsigned long long pol) {
    float4 v;
    asm volatile("ld.global.nc.L2::cache_hint.v4.f32 {%0,%1,%2,%3}, [%4], %5;"
                 : "=f"(v.x), "=f"(v.y), "=f"(v.z), "=f"(v.w) : "l"(p), "l"(pol));
    return v;
}

// ---- mbarrier / TMA bulk helpers (validated on sm_103a in round 9) ----
__device__ __forceinline__ void mbar_init(unsigned int m, unsigned int cnt) {
    asm volatile("mbarrier.init.shared.b64 [%0], %1;" :: "r"(m), "r"(cnt) : "memory");
}
__device__ __forceinline__ void mbar_expect_tx(unsigned int m, unsigned int tx) {
    asm volatile("mbarrier.arrive.expect_tx.shared.b64 _, [%0], %1;"
                 :: "r"(m), "r"(tx) : "memory");
}
__device__ __forceinline__ void mbar_wait(unsigned int m, unsigned int parity) {
    asm volatile(
        "{\n\t.reg .pred P;\n\t"
        "WL_%=:\n\t"
        "mbarrier.try_wait.parity.acquire.cta.shared::cta.b64 P, [%0], %1, 0x989680;\n\t"
        "@P bra.uni WD_%=;\n\t"
        "bra.uni WL_%=;\n\t"
        "WD_%=:\n\t}"
        :: "r"(m), "r"(parity) : "memory");
}
__device__ __forceinline__ void tma_bulk(unsigned int dst, const void* src,
                                         unsigned int bytes, unsigned int mbar) {
    asm volatile(
        "cp.async.bulk.shared::cluster.global.mbarrier::complete_tx::bytes [%0], [%1], %2, [%3];"
        :: "r"(dst), "l"(src), "r"(bytes), "r"(mbar) : "memory");
}

__global__ void init_kernel() {
    int j = blockIdx.x * blockDim.x + threadIdx.x;
    if (j < NN) {
        dR[j] = 0.f;
        dCs[j] = 0.f;
        dVh[j] = __float2half(0.00390625f);      // v_0 = 1, stored *2^-8
    }
    if (j == 0) dDot = 0.f;
}

// One pass over M and target: build K (e5m2), row/col sums of target, dot(target, M).
__global__ void __launch_bounds__(256) prep_kernel(const float* __restrict__ M,
                                                   const float* __restrict__ T) {
    __shared__ float sred[8 * 256];
    __shared__ float sdot_s[256];
    const unsigned long long pF = pol_first();
    const unsigned long long pL = pol_last();
    const int w = threadIdx.x >> 5, l = threadIdx.x & 31;
    const int col0 = blockIdx.x * 256 + l * 8;
    const int r0 = blockIdx.y * 256;
    const float SC = 10.0f * 1.4426950408889634f;

    float cs[8];
#pragma unroll
    for (int k = 0; k < 8; k++) cs[k] = 0.f;
    float dot = 0.f;

    for (int r = r0 + w; r < r0 + 256; r += 8) {
        size_t base = (size_t)r * NN + col0;
        float4 m0 = ldS(M + base, pF);
        float4 m1 = ldS(M + base + 4, pF);
        float4 t0 = ldS(T + base, pF);
        float4 t1 = ldS(T + base + 4, pF);

        union { uint2 u; __nv_fp8x2_storage_t s[4]; } P;
        P.s[0] = __nv_cvt_float2_to_fp8x2(make_float2(exp2f(m0.x * SC), exp2f(m0.y * SC)),
                                          __NV_SATFINITE, __NV_E5M2);
        P.s[1] = __nv_cvt_float2_to_fp8x2(make_float2(exp2f(m0.z * SC), exp2f(m0.w * SC)),
                                          __NV_SATFINITE, __NV_E5M2);
        P.s[2] = __nv_cvt_float2_to_fp8x2(make_float2(exp2f(m1.x * SC), exp2f(m1.y * SC)),
                                          __NV_SATFINITE, __NV_E5M2);
        P.s[3] = __nv_cvt_float2_to_fp8x2(make_float2(exp2f(m1.z * SC), exp2f(m1.w * SC)),
                                          __NV_SATFINITE, __NV_E5M2);
        stK(dK8 + base, P.u, pL);

        cs[0] += t0.x; cs[1] += t0.y; cs[2] += t0.z; cs[3] += t0.w;
        cs[4] += t1.x; cs[5] += t1.y; cs[6] += t1.z; cs[7] += t1.w;

        dot += m0.x * t0.x + m0.y * t0.y + m0.z * t0.z + m0.w * t0.w
             + m1.x * t1.x + m1.y * t1.y + m1.z * t1.z + m1.w * t1.w;

        float rs = t0.x + t0.y + t0.z + t0.w + t1.x + t1.y + t1.z + t1.w;
#pragma unroll
        for (int o = 16; o > 0; o >>= 1) rs += __shfl_xor_sync(0xffffffffu, rs, o);
        if (l == 0) atomicAdd(&dR[r], rs);
    }

#pragma unroll
    for (int k = 0; k < 8; k++) sred[w * 256 + l * 8 + k] = cs[k];
    sdot_s[threadIdx.x] = dot;
    __syncthreads();

    float s = 0.f;
#pragma unroll
    for (int w2 = 0; w2 < 8; w2++) s += sred[w2 * 256 + threadIdx.x];
    atomicAdd(&dCs[blockIdx.x * 256 + threadIdx.x], s);

    for (int off = 128; off > 0; off >>= 1) {
        if (threadIdx.x < off) sdot_s[threadIdx.x] += sdot_s[threadIdx.x + off];
        __syncthreads();
    }
    if (threadIdx.x == 0) atomicAdd(&dDot, sdot_s[0]);
}

// Fused Sinkhorn pair: one sweep over K computes u_i = a_i/(K_i.v) AND colAcc
// partials. 148 blocks (1/SM), 512 threads, thread owns 16 fixed columns.
// K staged through smem via TMA bulk copies (8 rows = 64KB/stage, double-buffered,
// mbarrier-completed) — replaces 4096 LDGSTS/batch with 4 bulk ops.
__global__ void __launch_bounds__(THREADS, 1)
fused_iter(const float* __restrict__ a, int iter) {
    extern __shared__ char smem[];
    unsigned int sbase;
    asm("{ .reg .u64 tmp; cvta.to.shared.u64 tmp, %1; cvt.u32.u64 %0, tmp; }"
        : "=r"(sbase) : "l"(smem));
    const unsigned int mbar0 = sbase + 2 * STAGE_BYTES;                    // two u64 mbarriers
    float* sa   = reinterpret_cast<float*>(smem + 2 * STAGE_BYTES + 16);   // [64]
    float* sdot = sa + 64;                                                 // [2][128]

    const int t = threadIdx.x;
    const int l = t & 31;
    const int w = t >> 5;
    const int c0 = t * 16;
    const int bid = blockIdx.x;
    const int r0 = (bid * NN) / NBLK;
    const int r1 = ((bid + 1) * NN) / NBLK;   // 55 or 56 rows

    if (t == 0) {
        mbar_init(mbar0, 1);
        mbar_init(mbar0 + 8, 1);
        asm volatile("fence.proxy.async.shared::cta;" ::: "memory");
    }
    if (t < 64) {
        int rr = r0 + t;
        sa[t] = (rr < r1) ? a[rr] * 0.00390625f : 0.f;   // a * 2^-8
    }
    __syncthreads();

    // prologue: fill both stages (batches 0, 1)
    if (t == 0) {
#pragma unroll
        for (int s = 0; s < 2; s++) {
            mbar_expect_tx(mbar0 + 8 * s, STAGE_BYTES);
            const unsigned char* src = dK8 + (size_t)(r0 + s * BATCH) * NN;
#pragma unroll
            for (int q = 0; q < 4; q++)
                tma_bulk(sbase + s * STAGE_BYTES + q * 16384, src + q * 16384,
                         16384, mbar0 + 8 * s);
        }
    }

    // v (scaled 2^-8) for my 16 columns -> 8 half2 regs
    union { uint4 q[2]; __half2 h[8]; } V;
    const uint4* vp = reinterpret_cast<const uint4*>(dVh + (size_t)iter * NN + c0);
    V.q[0] = vp[0];
    V.q[1] = vp[1];

    float facc[16];
#pragma unroll
    for (int i = 0; i < 16; i++) facc[i] = 0.f;

#pragma unroll 1
    for (int bt = 0; bt < NBATCH; bt++) {
        const int s = bt & 1;
        mbar_wait(mbar0 + 8 * s, (bt >> 1) & 1);

        const uint4* sp = reinterpret_cast<const uint4*>(smem + s * STAGE_BYTES) + t;
        uint4 kq[BATCH];
#pragma unroll
        for (int r = 0; r < BATCH; r++) kq[r] = sp[r * 512];

        // Phase A: per-row partial dots with v
        float dotp[BATCH];
#pragma unroll
        for (int r = 0; r < BATCH; r++) {
            __half2 hs = __hmul2(e5lo(kq[r].x), V.h[0]);
            hs = __hfma2(e5hi(kq[r].x), V.h[1], hs);
            hs = __hfma2(e5lo(kq[r].y), V.h[2], hs);
            hs = __hfma2(e5hi(kq[r].y), V.h[3], hs);
            hs = __hfma2(e5lo(kq[r].z), V.h[4], hs);
            hs = __hfma2(e5hi(kq[r].z), V.h[5], hs);
            hs = __hfma2(e5lo(kq[r].w), V.h[6], hs);
            hs = __hfma2(e5hi(kq[r].w), V.h[7], hs);
            float2 f = __half22float2(hs);
            dotp[r] = f.x + f.y;
        }
#pragma unroll
        for (int r = 0; r < BATCH; r++) {
#pragma unroll
            for (int o = 16; o > 0; o >>= 1)
                dotp[r] += __shfl_xor_sync(0xffffffffu, dotp[r], o);
        }
        const int par = bt & 1;
        if (l == 0) {
#pragma unroll
            for (int r = 0; r < BATCH; r++) sdot[par * 128 + r * 16 + w] = dotp[r];
        }
        __syncthreads();   // all threads consumed stage s (regs) AND sdot visible

        // refill stage s for batch bt+2 (single thread, 4 bulk ops)
        if (t == 0 && bt + 2 < NBATCH) {
            mbar_expect_tx(mbar0 + 8 * s, STAGE_BYTES);
            const unsigned char* src = dK8 + (size_t)(r0 + (bt + 2) * BATCH) * NN;
#pragma unroll
            for (int q = 0; q < 4; q++)
                tma_bulk(sbase + s * STAGE_BYTES + q * 16384, src + q * 16384,
                         16384, mbar0 + 8 * s);
        }

        // every warp redundantly reduces the 8x16 partials (no 2nd barrier)
        float x0 = sdot[par * 128 + l];          // rows 0,1
        float x1 = sdot[par * 128 + 32 + l];     // rows 2,3
        float x2 = sdot[par * 128 + 64 + l];     // rows 4,5
        float x3 = sdot[par * 128 + 96 + l];     // rows 6,7
#pragma unroll
        for (int o = 8; o > 0; o >>= 1) {
            x0 += __shfl_xor_sync(0xffffffffu, x0, o);
            x1 += __shfl_xor_sync(0xffffffffu, x1, o);
            x2 += __shfl_xor_sync(0xffffffffu, x2, o);
            x3 += __shfl_xor_sync(0xffffffffu, x3, o);
        }
        const int rb = r0 + bt * BATCH;
        const int half16 = l >> 4;                    // 0 or 1
        const int my0 = rb + 0 + half16;
        const int my1 = rb + 2 + half16;
        const int my2 = rb + 4 + half16;
        const int my3 = rb + 6 + half16;
        float u0 = (my0 < r1) ? __fdividef(sa[my0 - r0], x0) : 0.f;
        float u1 = (my1 < r1) ? __fdividef(sa[my1 - r0], x1) : 0.f;
        float u2 = (my2 < r1) ? __fdividef(sa[my2 - r0], x2) : 0.f;
        float u3 = (my3 < r1) ? __fdividef(sa[my3 - r0], x3) : 0.f;
        if (t == 0 || t == 16) {
            if (my0 < r1) dU[my0] = u0;
            if (my1 < r1) dU[my1] = u1;
            if (my2 < r1) dU[my2] = u2;
            if (my3 < r1) dU[my3] = u3;
        }
        const float S31 = 2147483648.0f;
        __half2 uh[BATCH];
        uh[0] = __float2half2_rn(__shfl_sync(0xffffffffu, u0, 0) * S31);
        uh[1] = __float2half2_rn(__shfl_sync(0xffffffffu, u0, 16) * S31);
        uh[2] = __float2half2_rn(__shfl_sync(0xffffffffu, u1, 0) * S31);
        uh[3] = __float2half2_rn(__shfl_sync(0xffffffffu, u1, 16) * S31);
        uh[4] = __float2half2_rn(__shfl_sync(0xffffffffu, u2, 0) * S31);
        uh[5] = __float2half2_rn(__shfl_sync(0xffffffffu, u2, 16) * S31);
        uh[6] = __float2half2_rn(__shfl_sync(0xffffffffu, u3, 0) * S31);
        uh[7] = __float2half2_rn(__shfl_sync(0xffffffffu, u3, 16) * S31);

        // Phase B: colAcc partials += K^T u (reuse kq regs)
        __half2 bacc[8];
#pragma unroll
        for (int i = 0; i < 8; i++) bacc[i] = __float2half2_rn(0.f);
#pragma unroll
        for (int r = 0; r < BATCH; r++) {
            bacc[0] = __hfma2(e5lo(kq[r].x), uh[r], bacc[0]);
            bacc[1] = __hfma2(e5hi(kq[r].x), uh[r], bacc[1]);
            bacc[2] = __hfma2(e5lo(kq[r].y), uh[r], bacc[2]);
            bacc[3] = __hfma2(e5hi(kq[r].y), uh[r], bacc[3]);
            bacc[4] = __hfma2(e5lo(kq[r].z), uh[r], bacc[4]);
            bacc[5] = __hfma2(e5hi(kq[r].z), uh[r], bacc[5]);
            bacc[6] = __hfma2(e5lo(kq[r].w), uh[r], bacc[6]);
            bacc[7] = __hfma2(e5hi(kq[r].w), uh[r], bacc[7]);
        }
#pragma unroll
        for (int i = 0; i < 8; i++) {
            float2 f = __half22float2(bacc[i]);
            facc[2 * i]     += f.x;
            facc[2 * i + 1] += f.y;
        }
    }

    float4* outp = reinterpret_cast<float4*>(&dScr[bid][c0]);
#pragma unroll
    for (int i = 0; i < 4; i++)
        outp[i] = make_float4(facc[4 * i], facc[4 * i + 1],
                              facc[4 * i + 2], facc[4 * i + 3]);
}

// Sum the 148 per-block partials per column — coalesced float4 version.
// 64 blocks x 512 threads: thread = (colgroup = t&31 [4 cols], sub = t>>5 [16 subs]);
// a warp reads 32 consecutive float4 (512B contiguous) per partial row.
__global__ void __launch_bounds__(512) finalize_iter(const float* __restrict__ b, int iter) {
    __shared__ float4 sred[16][32];
    const int cg  = threadIdx.x & 31;
    const int sub = threadIdx.x >> 5;
    const int colbase = blockIdx.x * 128;
    const int p0 = (sub * NBLK) >> 4;
    const int p1 = ((sub + 1) * NBLK) >> 4;
    float4 s = make_float4(0.f, 0.f, 0.f, 0.f);
    for (int p = p0; p < p1; p++) {
        float4 v = *reinterpret_cast<const float4*>(&dScr[p][colbase + cg * 4]);
        s.x += v.x; s.y += v.y; s.z += v.z; s.w += v.w;
    }
    sred[sub][cg] = s;
    __syncthreads();
    if (threadIdx.x < 128) {
        const int c = colbase + threadIdx.x;
        float tot = 0.f;
#pragma unroll
        for (int g = 0; g < 16; g++) {
            const float* r = reinterpret_cast<const float*>(&sred[g][threadIdx.x >> 2]);
            tot += r[threadIdx.x & 3];
        }
        tot *= (1.0f / 2147483648.0f);       // undo 2^31 u scale
        dColAccLast[c] = tot;
        dVh[(size_t)(iter + 1) * NN + c] =
            __float2half(__fdividef(b[c], tot) * 0.00390625f);
    }
}

// loss = -( dot(target,M)/eps + sum_i R_i ln u_i + sum_j C_j ln v_j )
__global__ void loss_kernel(const float* __restrict__ b, float* __restrict__ out) {
    __shared__ float sred[1024];
    float p = 0.f;
    for (int i = threadIdx.x; i < NN; i += 1024) {
        p += dR[i] * logf(dU[i]);
        p += dCs[i] * (logf(b[i]) - logf(dColAccLast[i]));
    }
    sred[threadIdx.x] = p;
    __syncthreads();
    for (int off = 512; off > 0; off >>= 1) {
        if (threadIdx.x < off) sred[threadIdx.x] += sred[threadIdx.x + off];
        __syncthreads();
    }
    if (threadIdx.x == 0) out[0] = -(sred[0] + dDot * (1.0f / EPSI));
}

extern "C" void kernel_launch(void* const* d_in, const int* in_sizes, int n_in,
                              void* d_out, int out_size) {
    const float* M = (const float*)d_in[0];
    const float* T = (const float*)d_in[1];
    const float* a = (const float*)d_in[2];
    const float* b = (const float*)d_in[3];
    float* out = (float*)d_out;

    static int smem_set = 0;
    if (!smem_set) {
        cudaFuncSetAttribute(fused_iter, cudaFuncAttributeMaxDynamicSharedMemorySize, SMEMSZ);
        smem_set = 1;
    }

    init_kernel<<<(NN + 255) / 256, 256>>>();
    prep_kernel<<<dim3(32, 32), 256>>>(M, T);
    for (int k = 0; k < NITERS; k++) {
        fused_iter<<<NBLK, THREADS, SMEMSZ>>>(a, k);
        finalize_iter<<<NN / 128, 512>>>(b, k);
    }
    loss_kernel<<<1, 1024>>>(b, out);
}